// round 17
// baseline (speedup 1.0000x reference)
#include <cuda_runtime.h>
#include <cuda_bf16.h>
#include <cstdint>

// ---------------------------------------------------------------------------
// RNN: h_t = tanh(X_t @ W_xh + b_h + h_{t-1} @ W_hh) ; y_t = h_t @ W_hq + b_q
// out = [outputs (T*B*O floats) | states (T*B*H floats)]
// T=512 B=64 H=1024 I=512 O=512
//
// R17: mma_gemm rebuilt as a double-buffered pipeline (stage c+1 during
// compute of c; 1 sync/iter; cp.async for B tiles). Recurrence and wsplit
// byte-identical to R16 (proven 3092us).
// ---------------------------------------------------------------------------

#define RT 512
#define RB 64
#define RH 1024
#define RI 512
#define RO 512

// per-CTA epoch flags (one 128B line each)
__device__ unsigned g_flag[64][32];
// h in mma A-frag layout: [pingpong][split][(ktile*4 + hb*2 + mt)*32+lane][q]
__device__ __align__(16) uint32_t g_hA[2][2][256 * 32 * 4];
// split+transposed weights: Wt[n][k] bf16
__device__ __align__(16) __nv_bfloat16 g_Wxh1t[RH * RI];
__device__ __align__(16) __nv_bfloat16 g_Wxh2t[RH * RI];
__device__ __align__(16) __nv_bfloat16 g_Whq1t[RO * RH];
__device__ __align__(16) __nv_bfloat16 g_Whq2t[RO * RH];
__device__ __align__(16) __nv_bfloat16 g_Whh1t[RH * RH];
__device__ __align__(16) __nv_bfloat16 g_Whh2t[RH * RH];

// ---- helpers ----
__device__ __forceinline__ unsigned long long pack2(float lo, float hi) {
    unsigned long long r;
    asm("mov.b64 %0, {%1, %2};" : "=l"(r) : "f"(lo), "f"(hi));
    return r;
}
__device__ __forceinline__ float2 unpack2(unsigned long long v) {
    float lo, hi;
    asm("mov.b64 {%0, %1}, %2;" : "=f"(lo), "=f"(hi) : "l"(v));
    return make_float2(lo, hi);
}
__device__ __forceinline__ unsigned long long add2(unsigned long long a,
                                                   unsigned long long b) {
    unsigned long long d;
    asm("add.rn.f32x2 %0, %1, %2;" : "=l"(d) : "l"(a), "l"(b));
    return d;
}
__device__ __forceinline__ void stcg32u(void* p, uint32_t v) {
    asm volatile("st.global.cg.u32 [%0], %1;" :: "l"(p), "r"(v));
}
__device__ __forceinline__ uint4 ldcg128(const void* p) {
    uint4 v;
    asm volatile("ld.global.cg.v4.u32 {%0,%1,%2,%3}, [%4];"
                 : "=r"(v.x), "=r"(v.y), "=r"(v.z), "=r"(v.w) : "l"(p));
    return v;
}
__device__ __forceinline__ void red_release_add(unsigned* p, unsigned v) {
    asm volatile("red.release.gpu.global.add.u32 [%0], %1;" :: "l"(p), "r"(v)
                 : "memory");
}
__device__ __forceinline__ unsigned ld_acquire(const unsigned* p) {
    unsigned v;
    asm volatile("ld.acquire.gpu.global.u32 %0, [%1];" : "=r"(v) : "l"(p)
                 : "memory");
    return v;
}
__device__ __forceinline__ uint32_t smem_u32(const void* p) {
    uint32_t a;
    asm("{ .reg .u64 t; cvta.to.shared.u64 t, %1; cvt.u32.u64 %0, t; }"
        : "=r"(a) : "l"(p));
    return a;
}
__device__ __forceinline__ uint32_t cvt2bf(float lo, float hi) {
    uint32_t r;
    asm("cvt.rn.bf16x2.f32 %0, %1, %2;" : "=r"(r) : "f"(hi), "f"(lo));
    return r;
}
__device__ __forceinline__ void ldm4(uint32_t* r, uint32_t addr) {
    asm volatile(
        "ldmatrix.sync.aligned.m8n8.x4.shared.b16 {%0,%1,%2,%3}, [%4];"
        : "=r"(r[0]), "=r"(r[1]), "=r"(r[2]), "=r"(r[3]) : "r"(addr));
}
__device__ __forceinline__ void mma_bf16(float* c, const uint32_t* a,
                                         uint32_t b0, uint32_t b1) {
    asm volatile(
        "mma.sync.aligned.m16n8k16.row.col.f32.bf16.bf16.f32 "
        "{%0,%1,%2,%3}, {%4,%5,%6,%7}, {%8,%9}, {%0,%1,%2,%3};"
        : "+f"(c[0]), "+f"(c[1]), "+f"(c[2]), "+f"(c[3])
        : "r"(a[0]), "r"(a[1]), "r"(a[2]), "r"(a[3]), "r"(b0), "r"(b1));
}
__device__ __forceinline__ void cpasync16(uint32_t smem, const void* gmem) {
    asm volatile("cp.async.cg.shared.global [%0], [%1], 16;"
                 :: "r"(smem), "l"(gmem) : "memory");
}

// ---------------------------------------------------------------------------
// wsplit: W[K,N] fp32 -> Wt1/Wt2[N,K] bf16 (transpose + 2-term split).
// ---------------------------------------------------------------------------
__global__ __launch_bounds__(256) void wsplit(
    const float* __restrict__ W, __nv_bfloat16* __restrict__ Wt1,
    __nv_bfloat16* __restrict__ Wt2, int K, int N, int reset)
{
    __shared__ float tile[32][33];
    const int tx = threadIdx.x & 31, ty = threadIdx.x >> 5;
    const int bx = blockIdx.x, by = blockIdx.y;
    if (reset && bx == 0 && by == 0 && ty == 0) {
#pragma unroll
        for (int c = tx; c < 64; c += 32) g_flag[c][0] = 0u;
    }
    const int n = bx * 32 + tx;
#pragma unroll
    for (int i = 0; i < 4; i++) {
        int k = by * 32 + ty + i * 8;
        tile[ty + i * 8][tx] = W[(size_t)k * N + n];
    }
    __syncthreads();
    const int k2 = by * 32 + tx;
#pragma unroll
    for (int i = 0; i < 4; i++) {
        int n2 = bx * 32 + ty + i * 8;
        float v = tile[tx][ty + i * 8];
        __nv_bfloat16 b1 = __float2bfloat16_rn(v);
        float r = v - __bfloat162float(b1);
        Wt1[(size_t)n2 * K + k2] = b1;
        Wt2[(size_t)n2 * K + k2] = __float2bfloat16_rn(r);
    }
}

// ---------------------------------------------------------------------------
// mma_gemm v2: double-buffered pipeline. C = A(fp32) @ Wt + bias.
// CTA 128x64, 256 thr, K-chunk 64. Buffers: [A1|A2|B1|B2] x2 (55296 B each).
// Per iter: issue A LDGs + B cp.asyncs for c+1; compute c; cvt+STS A(c+1);
// wait cp.async; one __syncthreads.
// ---------------------------------------------------------------------------
#define AS1 0
#define AS2 18432
#define BS1 36864
#define BS2 46080
#define BUFSZ 55296
#define BIAS_OFF 110592
#define MM_SMEM 110848
#define RSTR 144

__global__ __launch_bounds__(256) void mma_gemm(
    const float* __restrict__ A,
    const __nv_bfloat16* __restrict__ Bt1,
    const __nv_bfloat16* __restrict__ Bt2,
    const float* __restrict__ bias, float* __restrict__ C,
    int M, int N, int K)
{
    extern __shared__ __align__(16) char ts[];
    const uint32_t sb = smem_u32(ts);
    float* sBias = (float*)(ts + BIAS_OFF);

    const int tid = threadIdx.x;
    const int wid = tid >> 5;
    const int lane = tid & 31;
    const int n0 = blockIdx.x * 64;
    const int m0 = blockIdx.y * 128;

    const int mw = (wid & 3) * 32;
    const int nw = (wid >> 2) * 32;
    const int l16 = lane & 15;
    const int lhi = lane >> 4;

    if (tid < 64) sBias[tid] = bias[n0 + tid];

    float acc[2][4][4];
#pragma unroll
    for (int i = 0; i < 2; i++)
#pragma unroll
        for (int j = 0; j < 4; j++)
#pragma unroll
            for (int q = 0; q < 4; q++) acc[i][j][q] = 0.0f;

    const int sr = tid >> 4;        // A row base 0..15
    const int sc = tid & 15;        // A f4-col 0..15
    const int br = tid >> 3;        // B row 0..31
    const int bc = tid & 7;         // B u4-col 0..7

    float4 areg[8];

    // ---- staging helpers (macros keep reg naming simple) ----
#define LOAD_A(k0)                                                          \
    _Pragma("unroll")                                                       \
    for (int it = 0; it < 8; it++)                                          \
        areg[it] = *(const float4*)(A + (size_t)(m0 + sr + it * 16) * K +   \
                                    (k0) + sc * 4);

#define STS_A(base)                                                         \
    _Pragma("unroll")                                                       \
    for (int it = 0; it < 8; it++) {                                        \
        float4 v = areg[it];                                                \
        uint32_t p1a = cvt2bf(v.x, v.y);                                    \
        uint32_t p1b = cvt2bf(v.z, v.w);                                    \
        float fx = v.x - __uint_as_float(p1a << 16);                        \
        float fy = v.y - __uint_as_float(p1a & 0xFFFF0000u);                \
        float fz = v.z - __uint_as_float(p1b << 16);                        \
        float fw = v.w - __uint_as_float(p1b & 0xFFFF0000u);                \
        uint32_t p2a = cvt2bf(fx, fy);                                      \
        uint32_t p2b = cvt2bf(fz, fw);                                      \
        uint32_t off = (uint32_t)((sr + it * 16) * RSTR + sc * 8);          \
        *(unsigned long long*)(ts + (base) + AS1 + off) =                   \
            (unsigned long long)p1a | ((unsigned long long)p1b << 32);      \
        *(unsigned long long*)(ts + (base) + AS2 + off) =                   \
            (unsigned long long)p2a | ((unsigned long long)p2b << 32);      \
    }

#define CPASYNC_B(k0, base)                                                 \
    _Pragma("unroll")                                                       \
    for (int it = 0; it < 2; it++) {                                        \
        int r = br + it * 32;                                               \
        size_t go = (size_t)(n0 + r) * K + (k0) + bc * 8;                   \
        uint32_t so = (uint32_t)(r * RSTR + bc * 16);                       \
        cpasync16(sb + (base) + BS1 + so, Bt1 + go);                        \
        cpasync16(sb + (base) + BS2 + so, Bt2 + go);                        \
    }

    // prologue: stage chunk 0 into buffer 0
    LOAD_A(0);
    CPASYNC_B(0, 0);
    STS_A(0);
    asm volatile("cp.async.commit_group;" ::: "memory");
    asm volatile("cp.async.wait_group 0;" ::: "memory");
    __syncthreads();

    const int nch = K >> 6;
    for (int c = 0; c < nch; ++c) {
        const uint32_t cb = (uint32_t)(c & 1) * BUFSZ;
        const uint32_t nb = (uint32_t)((c + 1) & 1) * BUFSZ;

        // issue next chunk's loads early (overlap with compute)
        if (c + 1 < nch) {
            LOAD_A((c + 1) << 6);
            CPASYNC_B((c + 1) << 6, nb);
            asm volatile("cp.async.commit_group;" ::: "memory");
        }

        // compute chunk c from buffer cb
#pragma unroll
        for (int ks = 0; ks < 4; ks++) {
            const uint32_t kb = (uint32_t)((ks * 16 + lhi * 8) * 2);

            uint32_t a1[2][4], a2[2][4];
#pragma unroll
            for (int mf = 0; mf < 2; mf++) {
                uint32_t ao = cb + (uint32_t)((mw + mf * 16 + l16) * RSTR) + kb;
                ldm4(a1[mf], sb + AS1 + ao);
                ldm4(a2[mf], sb + AS2 + ao);
            }
            uint32_t b1[2][4], b2[2][4];
#pragma unroll
            for (int np = 0; np < 2; np++) {
                uint32_t bo = cb + (uint32_t)((nw + np * 16 + l16) * RSTR) + kb;
                ldm4(b1[np], sb + BS1 + bo);
                ldm4(b2[np], sb + BS2 + bo);
            }
#pragma unroll
            for (int mf = 0; mf < 2; mf++)
#pragma unroll
                for (int np = 0; np < 2; np++)
#pragma unroll
                    for (int hf = 0; hf < 2; hf++) {
                        float* cc = acc[mf][np * 2 + hf];
                        mma_bf16(cc, a1[mf], b1[np][hf], b1[np][hf + 2]);
                        mma_bf16(cc, a1[mf], b2[np][hf], b2[np][hf + 2]);
                        mma_bf16(cc, a2[mf], b1[np][hf], b1[np][hf + 2]);
                    }
        }

        // commit staged A for c+1, drain B cp.asyncs, single sync
        if (c + 1 < nch) {
            STS_A(nb);
            asm volatile("cp.async.wait_group 0;" ::: "memory");
        }
        __syncthreads();
    }

    const int g = lane >> 2;
    const int t = lane & 3;
#pragma unroll
    for (int mf = 0; mf < 2; mf++) {
#pragma unroll
        for (int nf = 0; nf < 4; nf++) {
            const int col = nw + nf * 8 + 2 * t;
            const float bx0 = sBias[col];
            const float bx1 = sBias[col + 1];
            const int row = m0 + mf * 16 + mw + g;
            float* cp = C + (size_t)row * N + n0 + col;
            float2 o0 = make_float2(acc[mf][nf][0] + bx0, acc[mf][nf][1] + bx1);
            float2 o1 = make_float2(acc[mf][nf][2] + bx0, acc[mf][nf][3] + bx1);
            *(float2*)cp = o0;
            *(float2*)(cp + (size_t)8 * N) = o1;
        }
    }
#undef LOAD_A
#undef STS_A
#undef CPASYNC_B
}

// ---------------------------------------------------------------------------
// rnn_rec_mma (byte-identical to R16, proven)
// ---------------------------------------------------------------------------
#define RW1 0
#define RW2 66048
#define RREDB 132096
#define REC_SMEM 197632

__global__ __launch_bounds__(512) void rnn_rec_mma(
    const __nv_bfloat16* __restrict__ Whh1,
    const __nv_bfloat16* __restrict__ Whh2,
    float* __restrict__ states)
{
    extern __shared__ __align__(16) char rs[];
    const uint32_t sb = smem_u32(rs);
    unsigned long long* Red = (unsigned long long*)(rs + RREDB);

    const int tid = threadIdx.x;
    const int ks = tid >> 5;
    const int lane = tid & 31;
    const int cid = blockIdx.x;
    const int hb = cid >> 5;
    const int cg = cid & 31;
    const int n0 = cg * 32;

    unsigned* myflag = &g_flag[hb * 32 + 2 * ks + (lane & 1)][0];

    for (int idx = tid; idx < 32 * 128; idx += 512) {
        int r = idx >> 7, c = idx & 127;
        *(uint4*)(rs + RW1 + r * 2064 + c * 16) =
            *(const uint4*)(Whh1 + (size_t)(n0 + r) * RH + c * 8);
        *(uint4*)(rs + RW2 + r * 2064 + c * 16) =
            *(const uint4*)(Whh2 + (size_t)(n0 + r) * RH + c * 8);
    }
    __syncthreads();

    {
        const int l = lane, s = ks;
        const int mt = s >> 3, nt = (s & 7) >> 1, rr = s & 1;
        const int row = hb * 32 + mt * 16 + rr * 8 + (l >> 2);
        const int col = n0 + nt * 8 + 2 * (l & 3);
        float* op = states + (size_t)row * RH + col;
        float2 xp = *(float2*)op;
        float v0 = tanhf(xp.x), v1 = tanhf(xp.y);
        *(float2*)op = make_float2(v0, v1);
        uint32_t q1 = cvt2bf(v0, v1);
        float e0 = v0 - __uint_as_float(q1 << 16);
        float e1 = v1 - __uint_as_float(q1 & 0xFFFF0000u);
        const int kt = cg * 2 + (nt >> 1);
        uint32_t idx = (uint32_t)(((kt * 4 + hb * 2 + mt) * 32 + l) * 4 +
                                  rr + 2 * (nt & 1));
        stcg32u(&g_hA[0][0][idx], q1);
        stcg32u(&g_hA[0][1][idx], cvt2bf(e0, e1));
    }
    __syncthreads();
    if (tid == 0) red_release_add(&g_flag[cid][0], 1u);

    for (int t = 1; t < RT; ++t) {
        const int pp_r = (t - 1) & 1;

        if (lane < 2) {
            while (ld_acquire(myflag) < (unsigned)t) {}
        }
        __syncwarp();

        float acc[2][4][4];
#pragma unroll
        for (int mt = 0; mt < 2; mt++)
#pragma unroll
            for (int nt = 0; nt < 4; nt++)
#pragma unroll
                for (int q = 0; q < 4; q++) acc[mt][nt][q] = 0.0f;

#pragma unroll
        for (int kt = 0; kt < 4; kt++) {
            uint4 A1[2], A2[2];
#pragma unroll
            for (int mt = 0; mt < 2; mt++) {
                uint32_t base = (uint32_t)(
                    (((ks * 4 + kt) * 4 + hb * 2 + mt) * 32 + lane) * 4);
                A1[mt] = ldcg128(&g_hA[pp_r][0][base]);
                A2[mt] = ldcg128(&g_hA[pp_r][1][base]);
            }
            uint32_t w1[2][4], w2[2][4];
#pragma unroll
            for (int p = 0; p < 2; p++) {
                uint32_t bo = (uint32_t)(
                    (p * 16 + (lane & 15)) * 2064 +
                    ((ks * 4 + kt) * 16 + (lane >> 4) * 8) * 2);
                ldm4(w1[p], sb + RW1 + bo);
                ldm4(w2[p], sb + RW2 + bo);
            }
#pragma unroll
            for (int mt = 0; mt < 2; mt++)
#pragma unroll
                for (int p = 0; p < 2; p++)
#pragma unroll
                    for (int ntl = 0; ntl < 2; ntl++) {
                        float* cc = acc[mt][p * 2 + ntl];
                        mma_bf16(cc, (const uint32_t*)&A1[mt],
                                 w1[p][ntl], w1[p][ntl + 2]);
                        mma_bf16(cc, (const uint32_t*)&A1[mt],
                                 w2[p][ntl], w2[p][ntl + 2]);
                        mma_bf16(cc, (const uint32_t*)&A2[mt],
                                 w1[p][ntl], w1[p][ntl + 2]);
                    }
        }

#pragma unroll
        for (int mt = 0; mt < 2; mt++)
#pragma unroll
            for (int nt = 0; nt < 4; nt++)
#pragma unroll
                for (int rr = 0; rr < 2; rr++) {
                    int s = mt * 8 + nt * 2 + rr;
                    Red[(size_t)(ks * 16 + s) * 32 + lane] =
                        pack2(acc[mt][nt][rr * 2], acc[mt][nt][rr * 2 + 1]);
                }
        __syncthreads();

        {
            const int l = lane, s = ks;
            unsigned long long sum = Red[(size_t)s * 32 + l];
#pragma unroll
            for (int q = 1; q < 16; q++)
                sum = add2(sum, Red[(size_t)(q * 16 + s) * 32 + l]);
            float2 f = unpack2(sum);

            const int mt = s >> 3, nt = (s & 7) >> 1, rr = s & 1;
            const int row = hb * 32 + mt * 16 + rr * 8 + (l >> 2);
            const int col = n0 + nt * 8 + 2 * (l & 3);
            float* op = states + (size_t)t * (RB * RH) + (size_t)row * RH + col;
            float2 xp = *(float2*)op;
            float v0 = tanhf(xp.x + f.x);
            float v1 = tanhf(xp.y + f.y);
            *(float2*)op = make_float2(v0, v1);

            uint32_t q1 = cvt2bf(v0, v1);
            float e0 = v0 - __uint_as_float(q1 << 16);
            float e1 = v1 - __uint_as_float(q1 & 0xFFFF0000u);
            const int kt = cg * 2 + (nt >> 1);
            uint32_t idx = (uint32_t)(((kt * 4 + hb * 2 + mt) * 32 + l) * 4 +
                                      rr + 2 * (nt & 1));
            stcg32u(&g_hA[t & 1][0][idx], q1);
            stcg32u(&g_hA[t & 1][1][idx], cvt2bf(e0, e1));
        }
        __syncthreads();

        if (tid == 0 && t < RT - 1) red_release_add(&g_flag[cid][0], 1u);
    }
}

// ---------------------------------------------------------------------------
extern "C" void kernel_launch(void* const* d_in, const int* in_sizes, int n_in,
                              void* d_out, int out_size)
{
    const float* X    = (const float*)d_in[0];
    const float* W_xh = (const float*)d_in[1];
    const float* W_hh = (const float*)d_in[2];
    const float* b_h  = (const float*)d_in[3];
    const float* W_hq = (const float*)d_in[4];
    const float* b_q  = (const float*)d_in[5];

    float* outputs = (float*)d_out;                      // [T*B, O]
    float* states  = outputs + (size_t)RT * RB * RO;     // [T*B, H]

    const int M = RT * RB;  // 32768

    __nv_bfloat16 *pWxh1, *pWxh2, *pWhq1, *pWhq2, *pWhh1, *pWhh2;
    cudaGetSymbolAddress((void**)&pWxh1, g_Wxh1t);
    cudaGetSymbolAddress((void**)&pWxh2, g_Wxh2t);
    cudaGetSymbolAddress((void**)&pWhq1, g_Whq1t);
    cudaGetSymbolAddress((void**)&pWhq2, g_Whq2t);
    cudaGetSymbolAddress((void**)&pWhh1, g_Whh1t);
    cudaGetSymbolAddress((void**)&pWhh2, g_Whh2t);

    cudaFuncSetAttribute(mma_gemm,
                         cudaFuncAttributeMaxDynamicSharedMemorySize, MM_SMEM);
    cudaFuncSetAttribute(rnn_rec_mma,
                         cudaFuncAttributeMaxDynamicSharedMemorySize, REC_SMEM);

    // weight transforms (first resets flag state)
    wsplit<<<dim3(RH / 32, RI / 32), 256>>>(W_xh, pWxh1, pWxh2, RI, RH, 1);
    wsplit<<<dim3(RO / 32, RH / 32), 256>>>(W_hq, pWhq1, pWhq2, RH, RO, 0);
    wsplit<<<dim3(RH / 32, RH / 32), 256>>>(W_hh, pWhh1, pWhh2, RH, RH, 0);

    // Xproj: states <- X @ W_xh + b_h
    mma_gemm<<<dim3(RH / 64, M / 128), 256, MM_SMEM>>>(
        X, pWxh1, pWxh2, b_h, states, M, RH, RI);

    // tensorized recurrence
    rnn_rec_mma<<<64, 512, REC_SMEM>>>(pWhh1, pWhh2, states);

    // outputs <- states @ W_hq + b_q
    mma_gemm<<<dim3(RO / 64, M / 128), 256, MM_SMEM>>>(
        states, pWhq1, pWhq2, b_q, outputs, M, RO, RH);
}